// round 14
// baseline (speedup 1.0000x reference)
#include <cuda_runtime.h>

// out[r,c] = x[r,c] * scale[c],  scale[c] = (u[c] >= 0.1f) ? vec[c]/0.9f : 0
// x: [131072, 1024] fp32. DRAM-pinned stream (512 MB read + 512 MB write,
// ~6.8 TB/s / 85-86% DRAM across all prior variants). This round: persistent
// single-wave grid (888 CTAs = ~6/SM x 148 SMs) with a grid-stride loop,
// eliminating ~22 wave transitions and their DRAM-occupancy dips. MLP=4
// front-batched loads per loop group (measured-best depth); fused scale setup
// (one per thread — stride is a multiple of DEPTH/4 so the column-quad is
// loop-invariant).

#define DEPTH 1024
#define P_DROP 0.1f

__global__ void __launch_bounds__(256)
fused_scale_persist_kernel(const float4* __restrict__ x,
                           const float4* __restrict__ vec4,
                           const float4* __restrict__ u4,
                           float4* __restrict__ out,
                           int n4) {
    int i0 = blockIdx.x * blockDim.x + threadIdx.x;
    const int S = gridDim.x * blockDim.x;   // 227,328 — multiple of 256

    // Column-quad index is invariant across all grid-stride iterations.
    int c4 = i0 & (DEPTH / 4 - 1);
    float4 vv = __ldg(&vec4[c4]);           // 4 KB set: L1/L2 resident
    float4 uu = __ldg(&u4[c4]);
    const float r = 1.0f / (1.0f - P_DROP);
    float4 s;
    s.x = (uu.x >= P_DROP) ? vv.x * r : 0.0f;
    s.y = (uu.y >= P_DROP) ? vv.y * r : 0.0f;
    s.z = (uu.z >= P_DROP) ? vv.z * r : 0.0f;
    s.w = (uu.w >= P_DROP) ? vv.w * r : 0.0f;

    // Main loop: groups of 4 front-batched loads (MLP=4, measured optimum).
    int i = i0;
    for (; i + 3 * S < n4; i += 4 * S) {
        float4 a0 = x[i];
        float4 a1 = x[i + S];
        float4 a2 = x[i + 2 * S];
        float4 a3 = x[i + 3 * S];
        a0.x *= s.x; a0.y *= s.y; a0.z *= s.z; a0.w *= s.w;
        a1.x *= s.x; a1.y *= s.y; a1.z *= s.z; a1.w *= s.w;
        a2.x *= s.x; a2.y *= s.y; a2.z *= s.z; a2.w *= s.w;
        a3.x *= s.x; a3.y *= s.y; a3.z *= s.z; a3.w *= s.w;
        out[i]         = a0;
        out[i + S]     = a1;
        out[i + 2 * S] = a2;
        out[i + 3 * S] = a3;
    }
    // Tail: up to 3 remaining strided elements.
    for (; i < n4; i += S) {
        float4 v = x[i];
        v.x *= s.x; v.y *= s.y; v.z *= s.z; v.w *= s.w;
        out[i] = v;
    }
}

extern "C" void kernel_launch(void* const* d_in, const int* in_sizes, int n_in,
                              void* d_out, int out_size) {
    const float* x   = (const float*)d_in[0];
    const float* vec = (const float*)d_in[1];
    const float* u   = (const float*)d_in[2];
    float* out = (float*)d_out;

    int n4 = out_size / 4;          // 33,554,432 float4 elements
    // Persistent single wave: 888 blocks ≈ 6 CTAs/SM on 148 SMs.
    fused_scale_persist_kernel<<<888, 256>>>(
        (const float4*)x, (const float4*)vec, (const float4*)u,
        (float4*)out, n4);
}

// round 15
// speedup vs baseline: 1.1297x; 1.1297x over previous
#include <cuda_runtime.h>

// out[r,c] = x[r,c] * scale[c],  scale[c] = (u[c] >= 0.1f) ? vec[c]/0.9f : 0
// x: [131072, 1024] fp32. DRAM-pinned stream (512 MB read + 512 MB write).
// FINAL — measured optimum on every axis:
//   fused single kernel (one graph node) beats 2-kernel split;
//   float4 (LDG.128) beats 256-bit v8 path;
//   default cache policy beats .cs streaming hints;
//   front-batch depth 4 beats 2 and 8 (L1tex queue contention at 8);
//   exact-fit multi-wave grid (16384x256x8) beats persistent single-wave
//   (persistent dropped DRAM 86% -> 78%: fewer threads = shallower chip-wide
//   outstanding-request pool).
// Kernel sits at the HBM read+write mix ceiling: ~6.8 TB/s, 85-86% DRAM.

#define DEPTH 1024
#define P_DROP 0.1f

__global__ void __launch_bounds__(256)
fused_scale8_mlp4_kernel(const float4* __restrict__ x,
                         const float4* __restrict__ vec4,
                         const float4* __restrict__ u4,
                         float4* __restrict__ out) {
    int i = blockIdx.x * blockDim.x + threadIdx.x;
    const int S = gridDim.x * blockDim.x;   // 4,194,304 — multiple of 256

    // All 8 elements this thread touches share one column-quad.
    int c4 = i & (DEPTH / 4 - 1);
    float4 vv = __ldg(&vec4[c4]);           // 4 KB set: L1/L2 resident
    float4 uu = __ldg(&u4[c4]);
    const float r = 1.0f / (1.0f - P_DROP);
    float4 s;
    s.x = (uu.x >= P_DROP) ? vv.x * r : 0.0f;
    s.y = (uu.y >= P_DROP) ? vv.y * r : 0.0f;
    s.z = (uu.z >= P_DROP) ? vv.z * r : 0.0f;
    s.w = (uu.w >= P_DROP) ? vv.w * r : 0.0f;

    // Exact fit: 8 elements as two groups of 4 front-batched loads (MLP=4).
#pragma unroll
    for (int g = 0; g < 2; g++) {
        int b = i + g * 4 * S;
        float4 a0 = x[b];
        float4 a1 = x[b + S];
        float4 a2 = x[b + 2 * S];
        float4 a3 = x[b + 3 * S];
        a0.x *= s.x; a0.y *= s.y; a0.z *= s.z; a0.w *= s.w;
        a1.x *= s.x; a1.y *= s.y; a1.z *= s.z; a1.w *= s.w;
        a2.x *= s.x; a2.y *= s.y; a2.z *= s.z; a2.w *= s.w;
        a3.x *= s.x; a3.y *= s.y; a3.z *= s.z; a3.w *= s.w;
        out[b]         = a0;
        out[b + S]     = a1;
        out[b + 2 * S] = a2;
        out[b + 3 * S] = a3;
    }
}

extern "C" void kernel_launch(void* const* d_in, const int* in_sizes, int n_in,
                              void* d_out, int out_size) {
    const float* x   = (const float*)d_in[0];
    const float* vec = (const float*)d_in[1];
    const float* u   = (const float*)d_in[2];
    float* out = (float*)d_out;

    // n4 = out_size/4 = 33,554,432; 16384 blocks * 256 threads * 8 = n4 exactly.
    fused_scale8_mlp4_kernel<<<16384, 256>>>(
        (const float4*)x, (const float4*)vec, (const float4*)u, (float4*)out);
}

// round 16
// speedup vs baseline: 1.1345x; 1.0043x over previous
#include <cuda_runtime.h>

// out[r,c] = x[r,c] * scale[c],  scale[c] = (u[c] >= 0.1f) ? vec[c]/0.9f : 0
// x: [131072, 1024] fp32. DRAM-pinned stream (512 MB read + 512 MB write,
// pinned at ~6.8 TB/s / 85-86% DRAM across all variants). Config identical to
// the certified-best fused kernel (8 float4/thread, MLP=4 groups, exact-fit
// grid, default cache policy); this round tests the one unmeasured axis:
// CTA shape 512 threads (4 CTAs/SM) vs 256 (8 CTAs/SM) — fewer independent
// per-CTA front-batch bursts contending in the L1tex queue.

#define DEPTH 1024
#define P_DROP 0.1f

__global__ void __launch_bounds__(512)
fused_scale8_mlp4_b512_kernel(const float4* __restrict__ x,
                              const float4* __restrict__ vec4,
                              const float4* __restrict__ u4,
                              float4* __restrict__ out) {
    int i = blockIdx.x * blockDim.x + threadIdx.x;
    const int S = gridDim.x * blockDim.x;   // 4,194,304 — multiple of 256

    // All 8 elements this thread touches share one column-quad.
    int c4 = i & (DEPTH / 4 - 1);
    float4 vv = __ldg(&vec4[c4]);           // 4 KB set: L1/L2 resident
    float4 uu = __ldg(&u4[c4]);
    const float r = 1.0f / (1.0f - P_DROP);
    float4 s;
    s.x = (uu.x >= P_DROP) ? vv.x * r : 0.0f;
    s.y = (uu.y >= P_DROP) ? vv.y * r : 0.0f;
    s.z = (uu.z >= P_DROP) ? vv.z * r : 0.0f;
    s.w = (uu.w >= P_DROP) ? vv.w * r : 0.0f;

    // Exact fit: 8 elements as two groups of 4 front-batched loads (MLP=4).
#pragma unroll
    for (int g = 0; g < 2; g++) {
        int b = i + g * 4 * S;
        float4 a0 = x[b];
        float4 a1 = x[b + S];
        float4 a2 = x[b + 2 * S];
        float4 a3 = x[b + 3 * S];
        a0.x *= s.x; a0.y *= s.y; a0.z *= s.z; a0.w *= s.w;
        a1.x *= s.x; a1.y *= s.y; a1.z *= s.z; a1.w *= s.w;
        a2.x *= s.x; a2.y *= s.y; a2.z *= s.z; a2.w *= s.w;
        a3.x *= s.x; a3.y *= s.y; a3.z *= s.z; a3.w *= s.w;
        out[b]         = a0;
        out[b + S]     = a1;
        out[b + 2 * S] = a2;
        out[b + 3 * S] = a3;
    }
}

extern "C" void kernel_launch(void* const* d_in, const int* in_sizes, int n_in,
                              void* d_out, int out_size) {
    const float* x   = (const float*)d_in[0];
    const float* vec = (const float*)d_in[1];
    const float* u   = (const float*)d_in[2];
    float* out = (float*)d_out;

    // n4 = out_size/4 = 33,554,432; 8192 blocks * 512 threads * 8 = n4 exactly.
    fused_scale8_mlp4_b512_kernel<<<8192, 512>>>(
        (const float4*)x, (const float4*)vec, (const float4*)u, (float4*)out);
}